// round 14
// baseline (speedup 1.0000x reference)
#include <cuda_runtime.h>
#include <cuda_bf16.h>
#include <math.h>
#include <stdint.h>

// Problem constants
#define DEPTH 12
#define E_DIM 256
#define F_DIM 128
#define H_DIM 8
#define HD 32
#define U_DIM 1000
#define I_DIM 1000
#define B_DIM 64
#define N_TOK 257                  // 2F+1
#define M_ROWS (B_DIM * N_TOK)     // 16448
#define M_PAD 16512                // 129*128 (pad rows: junk, never real outputs)
#define FF_DIM 1024
#define QKV_DIM 768

// ---------------- scratch (device globals; zero-init, no allocation) --------
__device__ float d_x[M_PAD * E_DIM];
__device__ float d_qkv[M_PAD * QKV_DIM];
__device__ float d_bqkv[DEPTH * QKV_DIM];
__device__ __nv_bfloat16 d_hH[M_PAD * E_DIM];
__device__ __nv_bfloat16 d_hL[M_PAD * E_DIM];
__device__ __nv_bfloat16 d_oH[M_PAD * E_DIM];
__device__ __nv_bfloat16 d_oL[M_PAD * E_DIM];
__device__ __nv_bfloat16 d_tH[M_PAD * FF_DIM];
__device__ __nv_bfloat16 d_tL[M_PAD * FF_DIM];
// packed bf16 hi/lo transposed weights: layout [l][N][K]
__device__ __nv_bfloat16 d_WqkvH[DEPTH * QKV_DIM * E_DIM];
__device__ __nv_bfloat16 d_WqkvL[DEPTH * QKV_DIM * E_DIM];
__device__ __nv_bfloat16 d_WoH[DEPTH * E_DIM * E_DIM];
__device__ __nv_bfloat16 d_WoL[DEPTH * E_DIM * E_DIM];
__device__ __nv_bfloat16 d_W1H[DEPTH * FF_DIM * E_DIM];
__device__ __nv_bfloat16 d_W1L[DEPTH * FF_DIM * E_DIM];
__device__ __nv_bfloat16 d_W2H[DEPTH * E_DIM * FF_DIM];
__device__ __nv_bfloat16 d_W2L[DEPTH * E_DIM * FF_DIM];

// ---------------- bf16 split helpers -----------------------------------------
__device__ __forceinline__ void bf16_split(float x, __nv_bfloat16& h, __nv_bfloat16& l) {
    h = __float2bfloat16(x);
    l = __float2bfloat16(x - __bfloat162float(h));
}

__device__ __forceinline__ void split2(float a, float b, unsigned& h, unsigned& l) {
    __nv_bfloat162 H, L;
    H.x = __float2bfloat16(a);
    H.y = __float2bfloat16(b);
    L.x = __float2bfloat16(a - __bfloat162float(H.x));
    L.y = __float2bfloat16(b - __bfloat162float(H.y));
    h = *(unsigned*)&H;
    l = *(unsigned*)&L;
}

// ---------------- fused weight/bias pack (single launch) ---------------------
#define NQKV (DEPTH * QKV_DIM * E_DIM)
#define NWO  (DEPTH * E_DIM * E_DIM)
#define NW1  (DEPTH * E_DIM * FF_DIM)
#define NW2  (DEPTH * FF_DIM * E_DIM)
#define NB   (DEPTH * QKV_DIM)
#define NPACK (NQKV + NWO + NW1 + NW2 + NB)

__global__ __launch_bounds__(256) void pack_all_kernel(
    const float* __restrict__ Wq, const float* __restrict__ Wk,
    const float* __restrict__ Wv, const float* __restrict__ Wo,
    const float* __restrict__ W1, const float* __restrict__ W2,
    const float* __restrict__ bq, const float* __restrict__ bk,
    const float* __restrict__ bv,
    __nv_bfloat16* __restrict__ WqkvH, __nv_bfloat16* __restrict__ WqkvL,
    __nv_bfloat16* __restrict__ WoH, __nv_bfloat16* __restrict__ WoL,
    __nv_bfloat16* __restrict__ W1H, __nv_bfloat16* __restrict__ W1L,
    __nv_bfloat16* __restrict__ W2H, __nv_bfloat16* __restrict__ W2L,
    float* __restrict__ bqkv)
{
    long long idx = (long long)blockIdx.x * 256 + threadIdx.x;
    if (idx >= NPACK) return;
    if (idx < NQKV) {
        int k = idx % E_DIM;
        int n = (idx / E_DIM) % QKV_DIM;
        int l = idx / ((long long)E_DIM * QKV_DIM);
        const float* W = (n < 256) ? Wq : (n < 512) ? Wk : Wv;
        float v = W[((long long)l * E_DIM + k) * E_DIM + (n & 255)];
        bf16_split(v, WqkvH[idx], WqkvL[idx]);
        return;
    }
    idx -= NQKV;
    if (idx < NWO) {
        int k = idx % E_DIM;
        int n = (idx / E_DIM) % E_DIM;
        int l = idx / ((long long)E_DIM * E_DIM);
        float v = Wo[((long long)l * E_DIM + k) * E_DIM + n];
        bf16_split(v, WoH[idx], WoL[idx]);
        return;
    }
    idx -= NWO;
    if (idx < NW1) {
        int k = idx % E_DIM;
        int n = (idx / E_DIM) % FF_DIM;
        int l = idx / ((long long)E_DIM * FF_DIM);
        float v = W1[((long long)l * E_DIM + k) * FF_DIM + n];
        bf16_split(v, W1H[idx], W1L[idx]);
        return;
    }
    idx -= NW1;
    if (idx < NW2) {
        int k = idx % FF_DIM;
        int n = (idx / FF_DIM) % E_DIM;
        int l = idx / ((long long)FF_DIM * E_DIM);
        float v = W2[((long long)l * FF_DIM + k) * E_DIM + n];
        bf16_split(v, W2H[idx], W2L[idx]);
        return;
    }
    idx -= NW2;
    {
        int n = idx % QKV_DIM;
        int l = idx / QKV_DIM;
        float v;
        if (n < 256)      v = bq[l * E_DIM + n];
        else if (n < 512) v = bk[l * E_DIM + (n - 256)];
        else              v = bv[l * E_DIM + (n - 512)];
        bqkv[idx] = v;
    }
}

// ---------------- embedding --------------------------------------------------
__global__ __launch_bounds__(256) void embed_kernel(
    const int* __restrict__ user, const int* __restrict__ item,
    const float* __restrict__ ut, const float* __restrict__ it,
    const float* __restrict__ cls, const float* __restrict__ pos,
    float* __restrict__ x)
{
    int n = blockIdx.x;
    int b = blockIdx.y;
    int e = threadIdx.x;
    float v;
    if (n == 0) {
        v = cls[e];
    } else if (n <= F_DIM) {
        int uid = user[b];
        v = ut[((size_t)e * U_DIM + uid) * F_DIM + (n - 1)];
    } else {
        int iid = item[b];
        v = it[((size_t)e * I_DIM + iid) * F_DIM + (n - 1 - F_DIM)];
    }
    x[((size_t)b * N_TOK + n) * E_DIM + e] = v + pos[(size_t)n * E_DIM + e];
}

// ---------------- layernorm: warp per row, emits bf16 hi/lo ------------------
__device__ __forceinline__ float warp_sum(float v) {
    #pragma unroll
    for (int o = 16; o > 0; o >>= 1) v += __shfl_xor_sync(0xffffffffu, v, o);
    return v;
}

__global__ __launch_bounds__(256) void layernorm_kernel(
    const float* __restrict__ x, const float* __restrict__ g,
    const float* __restrict__ b,
    __nv_bfloat16* __restrict__ outH, __nv_bfloat16* __restrict__ outL)
{
    int row  = blockIdx.x * 8 + (threadIdx.x >> 5);
    int lane = threadIdx.x & 31;
    const float4* xr = (const float4*)(x + (size_t)row * E_DIM);
    float4 v0 = xr[lane * 2];
    float4 v1 = xr[lane * 2 + 1];
    float s  = v0.x + v0.y + v0.z + v0.w + v1.x + v1.y + v1.z + v1.w;
    float ss = v0.x*v0.x + v0.y*v0.y + v0.z*v0.z + v0.w*v0.w
             + v1.x*v1.x + v1.y*v1.y + v1.z*v1.z + v1.w*v1.w;
    s  = warp_sum(s);
    ss = warp_sum(ss);
    float mean = s * (1.f / E_DIM);
    float var  = ss * (1.f / E_DIM) - mean * mean;
    float rstd = rsqrtf(var + 1e-5f);

    float vv[8] = {v0.x, v0.y, v0.z, v0.w, v1.x, v1.y, v1.z, v1.w};
    const float* gp = g + lane * 8;
    const float* bp = b + lane * 8;
    __nv_bfloat162 H[4], L[4];
    #pragma unroll
    for (int i = 0; i < 4; i++) {
        float y0 = (vv[2*i]   - mean) * rstd * gp[2*i]   + bp[2*i];
        float y1 = (vv[2*i+1] - mean) * rstd * gp[2*i+1] + bp[2*i+1];
        bf16_split(y0, H[i].x, L[i].x);
        bf16_split(y1, H[i].y, L[i].y);
    }
    __nv_bfloat162* oh = (__nv_bfloat162*)(outH + (size_t)row * E_DIM) + lane * 4;
    __nv_bfloat162* ol = (__nv_bfloat162*)(outL + (size_t)row * E_DIM) + lane * 4;
    #pragma unroll
    for (int i = 0; i < 4; i++) { oh[i] = H[i]; ol[i] = L[i]; }
}

// ---------------- tensor-core GEMM (bf16 3-term, 128x128, term-major) --------
#define GBM 128
#define GBN 128
#define GBK 32
#define AKP 40       // pitch: 80B rows, conflict-free 8-row LDSM phases
#define MATB (GBM * AKP * 2)          // bytes per matrix per stage (10240)
#define TG_SMEM (8 * MATB)            // 2 stages x 4 matrices = 81920 B

__device__ __forceinline__ void mma_bf16(float* c, const unsigned* a, const unsigned* b) {
    asm volatile(
        "mma.sync.aligned.m16n8k16.row.col.f32.bf16.bf16.f32 "
        "{%0,%1,%2,%3}, {%4,%5,%6,%7}, {%8,%9}, {%0,%1,%2,%3};\n"
        : "+f"(c[0]), "+f"(c[1]), "+f"(c[2]), "+f"(c[3])
        : "r"(a[0]), "r"(a[1]), "r"(a[2]), "r"(a[3]), "r"(b[0]), "r"(b[1]));
}

#define LDSM4(R, ADDR) \
    asm volatile("ldmatrix.sync.aligned.m8n8.x4.shared.b16 {%0,%1,%2,%3}, [%4];" \
        : "=r"((R)[0]), "=r"((R)[1]), "=r"((R)[2]), "=r"((R)[3]) : "r"(ADDR))

#define CP16(dst, src) \
    asm volatile("cp.async.cg.shared.global [%0], [%1], 16;" :: "r"(dst), "l"(src))
#define CP_COMMIT() asm volatile("cp.async.commit_group;" ::: "memory")
#define CP_WAIT(n)  asm volatile("cp.async.wait_group %0;" :: "n"(n) : "memory")

__global__ void __launch_bounds__(256, 2) tgemm_kernel(
    const __nv_bfloat16* __restrict__ AH, const __nv_bfloat16* __restrict__ AL,
    const __nv_bfloat16* __restrict__ WtH, const __nv_bfloat16* __restrict__ WtL,
    const float* __restrict__ bias, const float* __restrict__ res,
    float* __restrict__ Cf,
    __nv_bfloat16* __restrict__ Ch, __nv_bfloat16* __restrict__ Cl,
    int K, int N, int gelu)
{
    extern __shared__ char smem[];

    const int tid  = threadIdx.x;
    const int lane = tid & 31;
    const int wid  = tid >> 5;
    const int wm   = wid & 3;
    const int wn   = wid >> 2;
    const int br   = blockIdx.y * GBM;
    const int bc   = blockIdx.x * GBN;
    const int qrow = lane >> 2;
    const int qcol = (lane & 3) * 2;

    const int arow = tid >> 1;
    const int akh  = (tid & 1) * 16;
    const __nv_bfloat16* AHbase = AH + (size_t)(br + arow) * K + akh;
    const __nv_bfloat16* ALbase = AL + (size_t)(br + arow) * K + akh;
    const __nv_bfloat16* BHbase = WtH + (size_t)(bc + arow) * K + akh;
    const __nv_bfloat16* BLbase = WtL + (size_t)(bc + arow) * K + akh;

    const unsigned a_off = (unsigned)((wm * 32 + (lane & 7) + ((lane >> 3) & 1) * 8) * AKP
                                      + ((lane >> 4) & 1) * 8);
    const unsigned b_off = (unsigned)((wn * 64 + ((lane >> 4) & 1) * 8 + (lane & 7)) * AKP
                                      + ((lane >> 3) & 1) * 8);

    const unsigned sAH0 = (unsigned)__cvta_generic_to_shared(smem);
    const unsigned sAL0 = sAH0 + 2 * MATB;
    const unsigned sBH0 = sAH0 + 4 * MATB;
    const unsigned sBL0 = sAH0 + 6 * MATB;

    const unsigned dT = (unsigned)((arow * AKP + akh) * 2);

    float acc[2][8][4];
    #pragma unroll
    for (int i = 0; i < 2; i++)
        #pragma unroll
        for (int j = 0; j < 8; j++)
            #pragma unroll
            for (int r = 0; r < 4; r++) acc[i][j][r] = 0.f;

    auto cp_stage = [&](int k0, int s) {
        unsigned off = (unsigned)(s * MATB);
        CP16(sAH0 + off + dT,      AHbase + k0);
        CP16(sAH0 + off + dT + 16, AHbase + k0 + 8);
        CP16(sAL0 + off + dT,      ALbase + k0);
        CP16(sAL0 + off + dT + 16, ALbase + k0 + 8);
        CP16(sBH0 + off + dT,      BHbase + k0);
        CP16(sBH0 + off + dT + 16, BHbase + k0 + 8);
        CP16(sBL0 + off + dT,      BLbase + k0);
        CP16(sBL0 + off + dT + 16, BLbase + k0 + 8);
    };

    auto compute = [&](int s) {
        const unsigned off = (unsigned)(s * MATB);
        const unsigned aHs = sAH0 + off;
        const unsigned aLs = sAL0 + off;
        const unsigned bHs = sBH0 + off;
        const unsigned bLs = sBL0 + off;
        #pragma unroll
        for (int kk = 0; kk < 2; kk++) {
            const unsigned kb = kk * 16;
            unsigned aH[2][4], aL[2][4], bH[4][4], bL[4][4];
            #pragma unroll
            for (int ma = 0; ma < 2; ma++) {
                unsigned eoff = a_off + (unsigned)(ma * 16 * AKP) + kb;
                LDSM4(aH[ma], aHs + eoff * 2);
                LDSM4(aL[ma], aLs + eoff * 2);
            }
            #pragma unroll
            for (int p = 0; p < 4; p++) {
                unsigned eoff = b_off + (unsigned)(p * 16 * AKP) + kb;
                LDSM4(bH[p], bHs + eoff * 2);
                LDSM4(bL[p], bLs + eoff * 2);
            }
            #pragma unroll
            for (int ma = 0; ma < 2; ma++)
                #pragma unroll
                for (int na = 0; na < 8; na++)
                    mma_bf16(acc[ma][na], aH[ma], &bH[na >> 1][(na & 1) * 2]);
            #pragma unroll
            for (int ma = 0; ma < 2; ma++)
                #pragma unroll
                for (int na = 0; na < 8; na++)
                    mma_bf16(acc[ma][na], aL[ma], &bH[na >> 1][(na & 1) * 2]);
            #pragma unroll
            for (int ma = 0; ma < 2; ma++)
                #pragma unroll
                for (int na = 0; na < 8; na++)
                    mma_bf16(acc[ma][na], aH[ma], &bL[na >> 1][(na & 1) * 2]);
        }
    };

    const int nst = K / GBK;
    cp_stage(0, 0);
    CP_COMMIT();

    int s = 0;
    for (int k = 0; k < nst; k++) {
        CP_WAIT(0);
        __syncthreads();
        if (k + 1 < nst) {
            cp_stage((k + 1) * GBK, s ^ 1);
            CP_COMMIT();
        }
        compute(s);
        s ^= 1;
    }

    // epilogue
    #pragma unroll
    for (int ma = 0; ma < 2; ma++) {
        #pragma unroll
        for (int half = 0; half < 2; half++) {
            int gr = br + wm * 32 + ma * 16 + qrow + half * 8;
            #pragma unroll
            for (int na = 0; na < 8; na++) {
                int gc = bc + wn * 64 + na * 8 + qcol;
                float v0 = acc[ma][na][half * 2 + 0] + bias[gc];
                float v1 = acc[ma][na][half * 2 + 1] + bias[gc + 1];
                if (gelu) {
                    v0 = 0.5f * v0 * (1.0f + erff(v0 * 0.70710678118654752f));
                    v1 = 0.5f * v1 * (1.0f + erff(v1 * 0.70710678118654752f));
                }
                if (res) {
                    float2 r = *(const float2*)&res[(size_t)gr * N + gc];
                    v0 += r.x; v1 += r.y;
                }
                if (Cf) {
                    float2 ov = {v0, v1};
                    *(float2*)&Cf[(size_t)gr * N + gc] = ov;
                }
                if (Ch) {
                    __nv_bfloat162 Hh, Ll;
                    bf16_split(v0, Hh.x, Ll.x);
                    bf16_split(v1, Hh.y, Ll.y);
                    *(__nv_bfloat162*)&Ch[(size_t)gr * N + gc] = Hh;
                    *(__nv_bfloat162*)&Cl[(size_t)gr * N + gc] = Ll;
                }
            }
        }
    }
}

// ---------------- flash attention on tensor cores ----------------------------
// Block per (h, b, half). K (272x32, hi/lo) and V^T (32x280, hi/lo) in smem.
// blockIdx.z splits the 17 query tiles 9/8 so the per-warp tail is <= 2 tiles.
#define NKP 272
#define KSP 40
#define VTP 280
#define ATT_SMEM ((2 * NKP * KSP + 2 * 32 * VTP) * 2)

__global__ void __launch_bounds__(256, 2) attention_kernel(
    const float* __restrict__ qkv,
    __nv_bfloat16* __restrict__ oH, __nv_bfloat16* __restrict__ oL)
{
    extern __shared__ __nv_bfloat16 asmem[];
    __nv_bfloat16* KsH = asmem;
    __nv_bfloat16* KsL = KsH + NKP * KSP;
    __nv_bfloat16* VtH = KsL + NKP * KSP;
    __nv_bfloat16* VtL = VtH + 32 * VTP;

    const int h = blockIdx.x;
    const int b = blockIdx.y;
    const int z = blockIdx.z;
    const int tid = threadIdx.x;
    const int w = tid >> 5, lane = tid & 31;
    const int qrow = lane >> 2, qcol = (lane & 3) * 2;
    const size_t base = ((size_t)b * N_TOK) * QKV_DIM + h * HD;

    // K: rows = keys, cols = dims (coalesced loads)
    for (int idx = tid; idx < NKP * 16; idx += 256) {
        int key = idx >> 4, d2 = idx & 15;
        float2 kv = make_float2(0.f, 0.f);
        if (key < N_TOK)
            kv = *(const float2*)&qkv[base + (size_t)key * QKV_DIM + 256 + d2 * 2];
        unsigned hh, ll;
        split2(kv.x, kv.y, hh, ll);
        *(unsigned*)&KsH[key * KSP + d2 * 2] = hh;
        *(unsigned*)&KsL[key * KSP + d2 * 2] = ll;
    }
    // V^T: rows = dims, cols = keys
    for (int idx = tid; idx < NKP * 32; idx += 256) {
        int key = idx >> 5, d = idx & 31;
        float v = (key < N_TOK) ? qkv[base + (size_t)key * QKV_DIM + 512 + d] : 0.f;
        __nv_bfloat16 hh = __float2bfloat16(v);
        VtH[d * VTP + key] = hh;
        VtL[d * VTP + key] = __float2bfloat16(v - __bfloat162float(hh));
    }
    __syncthreads();

    const unsigned sKH = (unsigned)__cvta_generic_to_shared(KsH);
    const unsigned sKL = (unsigned)__cvta_generic_to_shared(KsL);
    const unsigned sVH = (unsigned)__cvta_generic_to_shared(VtH);
    const unsigned sVL = (unsigned)__cvta_generic_to_shared(VtL);
    const int ld_row = ((lane >> 4) & 1) * 8 + (lane & 7);
    const int ld_col = ((lane >> 3) & 1) * 8;

    const int qt_lo = (z == 0) ? 0 : 9;
    const int qt_hi = (z == 0) ? 9 : 17;

    for (int qt = qt_lo + w; qt < qt_hi; qt += 8) {
        const int q0 = qt * 16;

        // Q fragments straight from gmem (fp32 -> bf16 hi/lo)
        unsigned aQh[2][4], aQl[2][4];
        #pragma unroll
        for (int kk = 0; kk < 2; kk++)
            #pragma unroll
            for (int f = 0; f < 4; f++) {
                int row = q0 + qrow + (f & 1) * 8;
                int col = kk * 16 + qcol + (f >> 1) * 8;
                float2 qv = *(const float2*)&qkv[base + (size_t)row * QKV_DIM + col];
                split2(qv.x, qv.y, aQh[kk][f], aQl[kk][f]);
            }

        float m0 = -INFINITY, m1 = -INFINITY, s0 = 0.f, s1 = 0.f;
        float oa[4][4];
        #pragma unroll
        for (int na = 0; na < 4; na++)
            #pragma unroll
            for (int r = 0; r < 4; r++) oa[na][r] = 0.f;

        for (int kt = 0; kt < 17; kt++) {
            unsigned kh[2][4], kl[2][4];
            #pragma unroll
            for (int kk = 0; kk < 2; kk++) {
                unsigned eoff = (unsigned)((kt * 16 + ld_row) * KSP + kk * 16 + ld_col);
                LDSM4(kh[kk], sKH + eoff * 2);
                LDSM4(kl[kk], sKL + eoff * 2);
            }
            float sL[4] = {0.f, 0.f, 0.f, 0.f};
            float sR[4] = {0.f, 0.f, 0.f, 0.f};
            #pragma unroll
            for (int kk = 0; kk < 2; kk++) {
                mma_bf16(sL, aQh[kk], &kh[kk][0]);
                mma_bf16(sR, aQh[kk], &kh[kk][2]);
                mma_bf16(sL, aQl[kk], &kh[kk][0]);
                mma_bf16(sR, aQl[kk], &kh[kk][2]);
                mma_bf16(sL, aQh[kk], &kl[kk][0]);
                mma_bf16(sR, aQh[kk], &kl[kk][2]);
            }
            if (kt == 16) {   // keys 256..271: only 256 valid
                if (qcol != 0) { sL[0] = -INFINITY; sL[2] = -INFINITY; }
                sL[1] = -INFINITY; sL[3] = -INFINITY;
                sR[0] = -INFINITY; sR[1] = -INFINITY;
                sR[2] = -INFINITY; sR[3] = -INFINITY;
            }

            float vm0 = fmaxf(fmaxf(sL[0], sL[1]), fmaxf(sR[0], sR[1]));
            float vm1 = fmaxf(fmaxf(sL[2], sL[3]), fmaxf(sR[2], sR[3]));
            vm0 = fmaxf(vm0, __shfl_xor_sync(0xffffffffu, vm0, 1));
            vm0 = fmaxf(vm0, __shfl_xor_sync(0xffffffffu, vm0, 2));
            vm1 = fmaxf(vm1, __shfl_xor_sync(0xffffffffu, vm1, 1));
            vm1 = fmaxf(vm1, __shfl_xor_sync(0xffffffffu, vm1, 2));
            float mn0 = fmaxf(m0, vm0), mn1 = fmaxf(m1, vm1);
            float c0 = __expf(m0 - mn0), c1 = __expf(m1 - mn1);
            m0 = mn0; m1 = mn1;

            float p0 = __expf(sL[0] - m0), p1 = __expf(sL[1] - m0);
            float p2 = __expf(sL[2] - m1), p3 = __expf(sL[3] - m1);
            float r0 = __expf(sR[0] - m0), r1 = __expf(sR[1] - m0);
            float r2 = __expf(sR[2] - m1), r3 = __expf(sR[3] - m1);
            s0 = s0 * c0 + p0 + p1 + r0 + r1;
            s1 = s1 * c1 + p2 + p3 + r2 + r3;
            #pragma unroll
            for (int na = 0; na < 4; na++) {
                oa[na][0] *= c0; oa[na][1] *= c0;
                oa[na][2] *= c1; oa[na][3] *= c1;
            }

            unsigned aPh[4], aPl[4];
            split2(p0, p1, aPh[0], aPl[0]);
            split2(p2, p3, aPh[1], aPl[1]);
            split2(r0, r1, aPh[2], aPl[2]);
            split2(r2, r3, aPh[3], aPl[3]);

            unsigned vh[2][4], vl[2][4];
            #pragma unroll
            for (int pd = 0; pd < 2; pd++) {
                unsigned eoff = (unsigned)((pd * 16 + ld_row) * VTP + kt * 16 + ld_col);
                LDSM4(vh[pd], sVH + eoff * 2);
                LDSM4(vl[pd], sVL + eoff * 2);
            }
            #pragma unroll
            for (int na = 0; na < 4; na++) {
                const unsigned* bh = &vh[na >> 1][(na & 1) * 2];
                const unsigned* bl = &vl[na >> 1][(na & 1) * 2];
                mma_bf16(oa[na], aPh, bh);
                mma_bf16(oa[na], aPl, bh);
                mma_bf16(oa[na], aPh, bl);
            }
        }

        s0 += __shfl_xor_sync(0xffffffffu, s0, 1);
        s0 += __shfl_xor_sync(0xffffffffu, s0, 2);
        s1 += __shfl_xor_sync(0xffffffffu, s1, 1);
        s1 += __shfl_xor_sync(0xffffffffu, s1, 2);
        float sc0 = 1.f / (s0 * 16.0f);   // /sqrt(E) applied after softmax
        float sc1 = 1.f / (s1 * 16.0f);

        int row0 = q0 + qrow;
        int row1 = row0 + 8;
        #pragma unroll
        for (int na = 0; na < 4; na++) {
            size_t col = (size_t)h * HD + na * 8 + qcol;
            if (row0 < N_TOK) {
                unsigned hh, ll;
                split2(oa[na][0] * sc0, oa[na][1] * sc0, hh, ll);
                size_t o = ((size_t)b * N_TOK + row0) * E_DIM + col;
                *(unsigned*)&oH[o] = hh;
                *(unsigned*)&oL[o] = ll;
            }
            if (row1 < N_TOK) {
                unsigned hh, ll;
                split2(oa[na][2] * sc1, oa[na][3] * sc1, hh, ll);
                size_t o = ((size_t)b * N_TOK + row1) * E_DIM + col;
                *(unsigned*)&oH[o] = hh;
                *(unsigned*)&oL[o] = ll;
            }
        }
    }
}

// ---------------- mean-pool + head LN + linear -------------------------------
__global__ __launch_bounds__(256) void pool_head_kernel(
    const float* __restrict__ x, const float* __restrict__ g,
    const float* __restrict__ b, const float* __restrict__ W,
    const float* __restrict__ bias, float* __restrict__ out)
{
    int bb = blockIdx.x;
    int e = threadIdx.x;
    int w = e >> 5, lane = e & 31;
    float s = 0.f;
    const float* xb = x + (size_t)bb * N_TOK * E_DIM + e;
    #pragma unroll 4
    for (int n = 0; n < N_TOK; n++) s += xb[(size_t)n * E_DIM];
    float pooled = s * (1.0f / N_TOK);

    __shared__ float sA[8], sB[8];
    float s1 = warp_sum(pooled);
    float s2 = warp_sum(pooled * pooled);
    if (lane == 0) { sA[w] = s1; sB[w] = s2; }
    __syncthreads();
    float tot = 0.f, tot2 = 0.f;
    #pragma unroll
    for (int i = 0; i < 8; i++) { tot += sA[i]; tot2 += sB[i]; }
    float mean = tot * (1.f / E_DIM);
    float var = tot2 * (1.f / E_DIM) - mean * mean;
    float rstd = rsqrtf(var + 1e-5f);
    float y = (pooled - mean) * rstd * g[e] + b[e];
    float t = y * W[e];
    __syncthreads();
    float t1 = warp_sum(t);
    if (lane == 0) sA[w] = t1;
    __syncthreads();
    if (e == 0) {
        float tot3 = 0.f;
        #pragma unroll
        for (int i = 0; i < 8; i++) tot3 += sA[i];
        out[bb] = tot3 + bias[0];
    }
}

// ---------------- driver ------------------------------------------------------
extern "C" void kernel_launch(void* const* d_in, const int* in_sizes, int n_in,
                              void* d_out, int out_size)
{
    const int*   user    = (const int*)  d_in[0];
    const int*   item    = (const int*)  d_in[1];
    const float* ut      = (const float*)d_in[2];
    const float* it      = (const float*)d_in[3];
    const float* cls     = (const float*)d_in[4];
    const float* pos     = (const float*)d_in[5];
    const float* ln1_g   = (const float*)d_in[6];
    const float* ln1_b   = (const float*)d_in[7];
    const float* Wq      = (const float*)d_in[8];
    const float* bq      = (const float*)d_in[9];
    const float* Wk      = (const float*)d_in[10];
    const float* bk      = (const float*)d_in[11];
    const float* Wv      = (const float*)d_in[12];
    const float* bv      = (const float*)d_in[13];
    const float* Wo      = (const float*)d_in[14];
    const float* bo      = (const float*)d_in[15];
    const float* ln2_g   = (const float*)d_in[16];
    const float* ln2_b   = (const float*)d_in[17];
    const float* W1      = (const float*)d_in[18];
    const float* b1      = (const float*)d_in[19];
    const float* W2      = (const float*)d_in[20];
    const float* b2      = (const float*)d_in[21];
    const float* head_g  = (const float*)d_in[22];
    const float* head_b  = (const float*)d_in[23];
    const float* head_W  = (const float*)d_in[24];
    const float* head_bi = (const float*)d_in[25];

    float *x, *qkv, *bqkv;
    __nv_bfloat16 *hH, *hL, *oH, *oL, *tH, *tL;
    __nv_bfloat16 *WqkvH, *WqkvL, *WoH, *WoL, *W1H, *W1L, *W2H, *W2L;
    cudaGetSymbolAddress((void**)&x,     d_x);
    cudaGetSymbolAddress((void**)&qkv,   d_qkv);
    cudaGetSymbolAddress((void**)&bqkv,  d_bqkv);
    cudaGetSymbolAddress((void**)&hH,    d_hH);
    cudaGetSymbolAddress((void**)&hL,    d_hL);
    cudaGetSymbolAddress((void**)&oH,    d_oH);
    cudaGetSymbolAddress((void**)&oL,    d_oL);
    cudaGetSymbolAddress((void**)&tH,    d_tH);
    cudaGetSymbolAddress((void**)&tL,    d_tL);
    cudaGetSymbolAddress((void**)&WqkvH, d_WqkvH);
    cudaGetSymbolAddress((void**)&WqkvL, d_WqkvL);
    cudaGetSymbolAddress((void**)&WoH,   d_WoH);
    cudaGetSymbolAddress((void**)&WoL,   d_WoL);
    cudaGetSymbolAddress((void**)&W1H,   d_W1H);
    cudaGetSymbolAddress((void**)&W1L,   d_W1L);
    cudaGetSymbolAddress((void**)&W2H,   d_W2H);
    cudaGetSymbolAddress((void**)&W2L,   d_W2L);

    cudaFuncSetAttribute(attention_kernel,
                         cudaFuncAttributeMaxDynamicSharedMemorySize, ATT_SMEM);
    cudaFuncSetAttribute(tgemm_kernel,
                         cudaFuncAttributeMaxDynamicSharedMemorySize, TG_SMEM);

    // single fused pack launch
    pack_all_kernel<<<(int)((NPACK + 255LL) / 256), 256>>>(
        Wq, Wk, Wv, Wo, W1, W2, bq, bk, bv,
        WqkvH, WqkvL, WoH, WoL, W1H, W1L, W2H, W2L, bqkv);

    embed_kernel<<<dim3(N_TOK, B_DIM), 256>>>(user, item, ut, it, cls, pos, x);

    const dim3 gQKV(QKV_DIM / GBN, M_PAD / GBM);   // (6, 129)
    const dim3 gE(E_DIM / GBN, M_PAD / GBM);       // (2, 129)
    const dim3 gFF(FF_DIM / GBN, M_PAD / GBM);     // (8, 129)
    const int  lnGrid = M_ROWS / 8;                // 2056

    for (int l = 0; l < DEPTH; l++) {
        size_t eOff   = (size_t)l * E_DIM;
        size_t eeOff  = (size_t)l * E_DIM * E_DIM;
        size_t ffOff  = (size_t)l * E_DIM * FF_DIM;
        size_t qkvOff = (size_t)l * E_DIM * QKV_DIM;

        layernorm_kernel<<<lnGrid, 256>>>(x, ln1_g + eOff, ln1_b + eOff, hH, hL);

        tgemm_kernel<<<gQKV, 256, TG_SMEM>>>(hH, hL, WqkvH + qkvOff, WqkvL + qkvOff,
                                             bqkv + (size_t)l * QKV_DIM, nullptr,
                                             qkv, nullptr, nullptr, E_DIM, QKV_DIM, 0);

        attention_kernel<<<dim3(H_DIM, B_DIM, 2), 256, ATT_SMEM>>>(qkv, oH, oL);

        // x = x + (o @ Wo + bo)
        tgemm_kernel<<<gE, 256, TG_SMEM>>>(oH, oL, WoH + eeOff, WoL + eeOff,
                                           bo + eOff, x, x, nullptr, nullptr,
                                           E_DIM, E_DIM, 0);

        layernorm_kernel<<<lnGrid, 256>>>(x, ln2_g + eOff, ln2_b + eOff, hH, hL);

        // t = gelu(h @ W1 + b1)  (bf16 hi/lo output)
        tgemm_kernel<<<gFF, 256, TG_SMEM>>>(hH, hL, W1H + ffOff, W1L + ffOff,
                                            b1 + (size_t)l * FF_DIM, nullptr,
                                            nullptr, tH, tL, E_DIM, FF_DIM, 1);
        // x = x + (t @ W2 + b2)
        tgemm_kernel<<<gE, 256, TG_SMEM>>>(tH, tL, W2H + ffOff, W2L + ffOff,
                                           b2 + eOff, x, x, nullptr, nullptr,
                                           FF_DIM, E_DIM, 0);
    }

    pool_head_kernel<<<B_DIM, 256>>>(x, head_g, head_b, head_W, head_bi,
                                     (float*)d_out);
}